// round 14
// baseline (speedup 1.0000x reference)
#include <cuda_runtime.h>
#include <math.h>
#include <stdint.h>

#define EMBED   1024
#define NHEADS  16
#define HDIM    64
#define BATCH   2
#define QLEN    2048
#define CLEN    2048
#define MROWS   (BATCH * QLEN)   // 4096
#define KP      (EMBED / 2)      // 512 u32 pairs per row

__device__ __align__(16) uint32_t g_Xqh[MROWS * KP];
__device__ __align__(16) uint32_t g_Xch[MROWS * KP];
__device__ __align__(16) uint32_t g_Wt[4][EMBED * KP];   // transposed: [n][kp]
__device__ __align__(16) uint32_t g_Qh[MROWS * KP];      // Q * (0.125*log2e) fp16
__device__ __align__(16) uint32_t g_Kh[MROWS * KP];
__device__ __align__(16) uint32_t g_Vh[MROWS * KP];
__device__ __align__(16) uint32_t g_Ah[MROWS * KP];

__device__ __forceinline__ uint32_t f2h2(float lo, float hi) {
    uint32_t r;
    asm("cvt.rn.f16x2.f32 %0, %1, %2;" : "=r"(r) : "f"(hi), "f"(lo));
    return r;
}
__device__ __forceinline__ float ex2(float x) {
    float y;
    asm("ex2.approx.ftz.f32 %0, %1;" : "=f"(y) : "f"(x));
    return y;
}
__device__ __forceinline__ uint32_t smem_u32(const void* p) {
    return (uint32_t)__cvta_generic_to_shared(p);
}
__device__ __forceinline__ void cp16(uint32_t saddr, const void* g) {
    asm volatile("cp.async.cg.shared.global [%0], [%1], 16;" :: "r"(saddr), "l"(g));
}
#define CP_COMMIT() asm volatile("cp.async.commit_group;" ::: "memory")
#define CP_WAIT(n)  asm volatile("cp.async.wait_group %0;" :: "n"(n) : "memory")

#define LDSM4(r0, r1, r2, r3, a)                                           \
    asm volatile("ldmatrix.sync.aligned.m8n8.x4.shared.b16 {%0,%1,%2,%3}, [%4];" \
        : "=r"(r0), "=r"(r1), "=r"(r2), "=r"(r3) : "r"(a))
#define LDSM4T(r0, r1, r2, r3, a)                                          \
    asm volatile("ldmatrix.sync.aligned.m8n8.x4.trans.shared.b16 {%0,%1,%2,%3}, [%4];" \
        : "=r"(r0), "=r"(r1), "=r"(r2), "=r"(r3) : "r"(a))

#define MMA_F16R(d, a0, a1, a2, a3, b0, b1)                                \
    asm volatile(                                                          \
        "mma.sync.aligned.m16n8k16.row.col.f32.f16.f16.f32 "               \
        "{%0,%1,%2,%3}, {%4,%5,%6,%7}, {%8,%9}, {%0,%1,%2,%3};"            \
        : "+f"(d[0]), "+f"(d[1]), "+f"(d[2]), "+f"(d[3])                   \
        : "r"(a0), "r"(a1), "r"(a2), "r"(a3), "r"(b0), "r"(b1))

// ---------------------------------------------------------------------------
// Prepass (single launch): z=0,1 pack inputs; z=2..5 transpose+pack weights.
// ---------------------------------------------------------------------------
__global__ void __launch_bounds__(256) prepack_kernel(
    const float* __restrict__ q, const float* __restrict__ ctx,
    const float* __restrict__ Wq, const float* __restrict__ Wk,
    const float* __restrict__ Wv, const float* __restrict__ Wo)
{
    const int z = blockIdx.z;
    const int tid = threadIdx.x;

    if (z < 2) {
        const float* src = (z == 0) ? q : ctx;
        uint2* dst = (uint2*)((z == 0) ? g_Xqh : g_Xch);
        const int blk = blockIdx.y * gridDim.x + blockIdx.x;
        const int stride = gridDim.x * gridDim.y * 256;
        const int count = MROWS * KP / 2;
        for (int i = blk * 256 + tid; i < count; i += stride) {
            float4 v = ((const float4*)src)[i];
            dst[i] = make_uint2(f2h2(v.x, v.y), f2h2(v.z, v.w));
        }
    } else {
        __shared__ float ws[64][33];
        const float* W = (z == 2) ? Wq : (z == 3) ? Wk : (z == 4) ? Wv : Wo;
        uint32_t* Wt = g_Wt[z - 2];
        const int kb = blockIdx.x * 64;
        const int nb = blockIdx.y * 32;
        #pragma unroll
        for (int i = 0; i < 8; i++) {
            int idx = tid + i * 256;
            int r = idx >> 5;
            int c = idx & 31;
            ws[r][c] = W[(size_t)(kb + r) * EMBED + nb + c];
        }
        __syncthreads();
        #pragma unroll
        for (int i = 0; i < 4; i++) {
            int idx = tid + i * 256;
            int n  = idx >> 5;
            int kp = idx & 31;
            Wt[(size_t)(nb + n) * KP + (kb >> 1) + kp] =
                f2h2(ws[2 * kp][n], ws[2 * kp + 1][n]);
        }
    }
}

// ---------------------------------------------------------------------------
// fp16 GEMM + bias: 3-stage cp.async ring, BK=32.
// CTA 64x128, 128 threads (4 warps 2x2), warp tile 32x64.
// Small CTA => 4 CTAs/SM = 4 independent barrier domains.
// ---------------------------------------------------------------------------
#define NSTG 3
#define PT   20                         // 16 data u32 + 4 pad
#define ASTG (64 * PT)                  // 1280 u32
#define BSTG (128 * PT)                 // 2560 u32
#define GSMEM ((NSTG * (ASTG + BSTG)) * 4)   // 46080 B

__device__ __forceinline__ void gemm_h_body(
    const uint32_t* __restrict__ A, const uint32_t* __restrict__ Wt,
    const float* __restrict__ bias, void* __restrict__ Cout,
    int outHalf, float oscale, int bx, int by)
{
    extern __shared__ uint32_t gsm[];
    uint32_t* As = gsm;                 // [NSTG][64][PT]
    uint32_t* Bs = gsm + NSTG * ASTG;   // [NSTG][128][PT]
    const uint32_t sAs = smem_u32(As);
    const uint32_t sBs = smem_u32(Bs);

    const int tid  = threadIdx.x;
    const int lane = tid & 31;
    const int warp = tid >> 5;           // 0..3
    const int g    = lane >> 2;
    const int tg   = lane & 3;
    const int wr   = (warp >> 1) * 32;   // 0,32
    const int wc   = (warp & 1) * 64;    // 0,64
    const int rowBase = by * 64;
    const int colBase = bx * 128;
    const int KT = 32;                   // 1024 / 32

    // ldmatrix lane addressing
    const int arow  = wr + ((lane >> 3) & 1) * 8 + (lane & 7);   // + mt*16
    const int ahalf = ((lane >> 4) & 1) * 4;
    const int brow  = wc + ((lane >> 4) & 1) * 8 + (lane & 7);   // + ntp*16
    const int bhalf = ((lane >> 3) & 1) * 4;

    // cp.async: A stage 256 uint4 chunks (2/thread); B stage 512 (4/thread)
    const int ar0 = (2 * tid) >> 2,     ac0 = ((2 * tid) & 3) * 4;
    const int ar1 = (2 * tid + 1) >> 2, ac1 = ((2 * tid + 1) & 3) * 4;
    int brw[4], bcl[4];
    #pragma unroll
    for (int i = 0; i < 4; i++) {
        int c = 4 * tid + i;
        brw[i] = c >> 2;
        bcl[i] = (c & 3) * 4;
    }

    auto issue = [&](int stg, int kt) {
        uint32_t sa = sAs + (uint32_t)(stg * ASTG) * 4;
        uint32_t sb = sBs + (uint32_t)(stg * BSTG) * 4;
        cp16(sa + (uint32_t)(ar0 * PT + ac0) * 4,
             A + (size_t)(rowBase + ar0) * KP + kt * 16 + ac0);
        cp16(sa + (uint32_t)(ar1 * PT + ac1) * 4,
             A + (size_t)(rowBase + ar1) * KP + kt * 16 + ac1);
        #pragma unroll
        for (int i = 0; i < 4; i++)
            cp16(sb + (uint32_t)(brw[i] * PT + bcl[i]) * 4,
                 Wt + (size_t)(colBase + brw[i]) * KP + kt * 16 + bcl[i]);
        CP_COMMIT();
    };

    float acc[2][8][4];
    #pragma unroll
    for (int mt = 0; mt < 2; mt++)
        #pragma unroll
        for (int nt = 0; nt < 8; nt++)
            #pragma unroll
            for (int e = 0; e < 4; e++) acc[mt][nt][e] = 0.f;

    issue(0, 0);
    issue(1, 1);

    for (int kt = 0; kt < KT; kt++) {
        const int stg = kt % NSTG;
        if (kt + 1 < KT) { CP_WAIT(1); } else { CP_WAIT(0); }
        __syncthreads();

        const uint32_t aBase = sAs + (uint32_t)(stg * ASTG) * 4;
        const uint32_t bBase = sBs + (uint32_t)(stg * BSTG) * 4;

        #pragma unroll
        for (int s = 0; s < 2; s++) {
            uint32_t a[2][4];
            #pragma unroll
            for (int mt = 0; mt < 2; mt++)
                LDSM4(a[mt][0], a[mt][1], a[mt][2], a[mt][3],
                      aBase + (uint32_t)(((arow + mt * 16) * PT) + 8 * s + ahalf) * 4);
            #pragma unroll
            for (int ntp = 0; ntp < 4; ntp++) {
                uint32_t b0, b1, b2, b3;
                LDSM4(b0, b1, b2, b3,
                      bBase + (uint32_t)(((brow + ntp * 16) * PT) + 8 * s + bhalf) * 4);
                #pragma unroll
                for (int mt = 0; mt < 2; mt++) {
                    MMA_F16R(acc[mt][2 * ntp],     a[mt][0], a[mt][1], a[mt][2], a[mt][3], b0, b1);
                    MMA_F16R(acc[mt][2 * ntp + 1], a[mt][0], a[mt][1], a[mt][2], a[mt][3], b2, b3);
                }
            }
        }
        if (kt + 2 < KT) issue((kt + 2) % NSTG, kt + 2);
    }

    if (outHalf) {
        uint32_t* C = (uint32_t*)Cout;
        #pragma unroll
        for (int mt = 0; mt < 2; mt++) {
            #pragma unroll
            for (int nt = 0; nt < 8; nt++) {
                int row  = rowBase + wr + mt * 16 + g;
                int col  = colBase + wc + nt * 8 + 2 * tg;
                int colp = col >> 1;
                float2 bv = *(const float2*)&bias[col];
                C[(size_t)row * KP + colp] =
                    f2h2((acc[mt][nt][0] + bv.x) * oscale,
                         (acc[mt][nt][1] + bv.y) * oscale);
                C[(size_t)(row + 8) * KP + colp] =
                    f2h2((acc[mt][nt][2] + bv.x) * oscale,
                         (acc[mt][nt][3] + bv.y) * oscale);
            }
        }
    } else {
        float* C = (float*)Cout;
        #pragma unroll
        for (int mt = 0; mt < 2; mt++) {
            #pragma unroll
            for (int nt = 0; nt < 8; nt++) {
                int row = rowBase + wr + mt * 16 + g;
                int col = colBase + wc + nt * 8 + 2 * tg;
                float2 bv = *(const float2*)&bias[col];
                float2 r0 = make_float2(acc[mt][nt][0] + bv.x, acc[mt][nt][1] + bv.y);
                float2 r1 = make_float2(acc[mt][nt][2] + bv.x, acc[mt][nt][3] + bv.y);
                *(float2*)&C[(size_t)row * EMBED + col]       = r0;
                *(float2*)&C[(size_t)(row + 8) * EMBED + col] = r1;
            }
        }
    }
}

#define QSCALE (0.125f * 1.44269504f)

__global__ void __launch_bounds__(128, 4) gemm_qkv_kernel(
    const float* __restrict__ bq, const float* __restrict__ bk,
    const float* __restrict__ bv)
{
    const int z = blockIdx.z;
    if (z == 0)      gemm_h_body(g_Xqh, g_Wt[0], bq, g_Qh, 1, QSCALE, blockIdx.x, blockIdx.y);
    else if (z == 1) gemm_h_body(g_Xch, g_Wt[1], bk, g_Kh, 1, 1.0f,   blockIdx.x, blockIdx.y);
    else             gemm_h_body(g_Xch, g_Wt[2], bv, g_Vh, 1, 1.0f,   blockIdx.x, blockIdx.y);
}

__global__ void __launch_bounds__(128, 4) gemm_o_kernel(
    const float* __restrict__ bo, float* __restrict__ out)
{
    gemm_h_body(g_Ah, g_Wt[3], bo, out, 0, 1.0f, blockIdx.x, blockIdx.y);
}

// ---------------------------------------------------------------------------
// Flash attention fp16 (R12 best, unchanged): 8 warps x 16 q-rows,
// 3-stage cp.async KV ring, one barrier per tile, ones-MMA row sums,
// P in registers, exp2-domain softmax.
// ---------------------------------------------------------------------------
#define FST  3
#define PKH 36
#define PPH 36
#define FSM_TOTAL ((FST * 2 * 64 * PKH + 128 * PPH) * 4)   // 73728 B

__global__ void __launch_bounds__(256, 2) flash_h_kernel()
{
    extern __shared__ uint32_t sm[];
    uint32_t* Ks = sm;
    uint32_t* Vs = sm + FST * 64 * PKH;
    uint32_t* Qstage = sm + 2 * FST * 64 * PKH;

    const int b  = blockIdx.z;
    const int h  = blockIdx.y;
    const int q0 = blockIdx.x * 128;
    const int tid  = threadIdx.x;
    const int lane = tid & 31;
    const int warp = tid >> 5;
    const int g    = lane >> 2;
    const int tg   = lane & 3;
    const int mrow = warp * 16;

    const int krow  = ((lane >> 4) & 1) * 8 + (lane & 7);
    const int khalf = ((lane >> 3) & 1) * 4;
    const int vk = ((lane >> 3) & 1) * 8 + (lane & 7);
    const int vd = ((lane >> 4) & 1) * 4;

    const uint32_t* Qb = g_Qh + (size_t)b * QLEN * KP + h * 32;
    const uint32_t* Kb = g_Kh + (size_t)b * CLEN * KP + h * 32;
    const uint32_t* Vb = g_Vh + (size_t)b * CLEN * KP + h * 32;

    const int c0 = 2 * tid, c1 = 2 * tid + 1;
    const int cr0 = c0 >> 3, cc0 = (c0 & 7) * 4;
    const int cr1 = c1 >> 3, cc1 = (c1 & 7) * 4;
    const uint32_t sKs = smem_u32(Ks);
    const uint32_t sVs = smem_u32(Vs);

    auto issueKV = [&](int stg, int kt) {
        uint32_t ks = sKs + (uint32_t)(stg * 64 * PKH) * 4;
        uint32_t vs = sVs + (uint32_t)(stg * 64 * PKH) * 4;
        cp16(ks + (uint32_t)(cr0 * PKH + cc0) * 4, Kb + (size_t)(kt * 64 + cr0) * KP + cc0);
        cp16(ks + (uint32_t)(cr1 * PKH + cc1) * 4, Kb + (size_t)(kt * 64 + cr1) * KP + cc1);
        cp16(vs + (uint32_t)(cr0 * PKH + cc0) * 4, Vb + (size_t)(kt * 64 + cr0) * KP + cc0);
        cp16(vs + (uint32_t)(cr1 * PKH + cc1) * 4, Vb + (size_t)(kt * 64 + cr1) * KP + cc1);
        CP_COMMIT();
    };

    #pragma unroll
    for (int i = 0; i < 4; i++) {
        int idx = tid + i * 256;
        int r = idx >> 3;
        int c = (idx & 7) * 4;
        uint4 v = *(const uint4*)&Qb[(size_t)(q0 + r) * KP + c];
        *(uint4*)&Qstage[r * PPH + c] = v;
    }
    issueKV(0, 0);
    issueKV(1, 1);
    __syncthreads();

    uint32_t qf[4][4];
    #pragma unroll
    for (int s = 0; s < 4; s++) {
        qf[s][0] = Qstage[(mrow + g) * PPH + 8 * s + tg];
        qf[s][1] = Qstage[(mrow + g + 8) * PPH + 8 * s + tg];
        qf[s][2] = Qstage[(mrow + g) * PPH + 8 * s + tg + 4];
        qf[s][3] = Qstage[(mrow + g + 8) * PPH + 8 * s + tg + 4];
    }

    const uint32_t ONES = 0x3C003C00u;
    float m0 = -INFINITY, m1 = -INFINITY, l0 = 0.f, l1 = 0.f;
    float o[8][4];
    #pragma unroll
    for (int nt = 0; nt < 8; nt++)
        #pragma unroll
        for (int e = 0; e < 4; e++) o[nt][e] = 0.f;

    const int NT = CLEN / 64;
    for (int kt = 0; kt < NT; kt++) {
        const int stg = kt % FST;
        if (kt + 1 < NT) { CP_WAIT(1); } else { CP_WAIT(0); }
        __syncthreads();
        if (kt + 2 < NT) issueKV((kt + 2) % FST, kt + 2);

        const uint32_t kBase = sKs + (uint32_t)(stg * 64 * PKH + krow * PKH + khalf) * 4;
        const uint32_t vBase = sVs + (uint32_t)(stg * 64 * PKH + vk * PKH + vd) * 4;

        float sacc[8][4];
        #pragma unroll
        for (int nt = 0; nt < 8; nt++)
            #pragma unroll
            for (int e = 0; e < 4; e++) sacc[nt][e] = 0.f;

        #pragma unroll
        for (int s = 0; s < 4; s++) {
            #pragma unroll
            for (int ntp = 0; ntp < 4; ntp++) {
                uint32_t b0, b1, b2, b3;
                LDSM4(b0, b1, b2, b3, kBase + (uint32_t)(ntp * 16 * PKH + 8 * s) * 4);
                MMA_F16R(sacc[2 * ntp],     qf[s][0], qf[s][1], qf[s][2], qf[s][3], b0, b1);
                MMA_F16R(sacc[2 * ntp + 1], qf[s][0], qf[s][1], qf[s][2], qf[s][3], b2, b3);
            }
        }

        float mx0 = -INFINITY, mx1 = -INFINITY;
        #pragma unroll
        for (int nt = 0; nt < 8; nt++) {
            mx0 = fmaxf(mx0, fmaxf(sacc[nt][0], sacc[nt][1]));
            mx1 = fmaxf(mx1, fmaxf(sacc[nt][2], sacc[nt][3]));
        }
        #pragma unroll
        for (int off = 1; off < 4; off <<= 1) {
            mx0 = fmaxf(mx0, __shfl_xor_sync(0xffffffffu, mx0, off));
            mx1 = fmaxf(mx1, __shfl_xor_sync(0xffffffffu, mx1, off));
        }
        float mn0 = fmaxf(m0, mx0), mn1 = fmaxf(m1, mx1);
        float corr0 = ex2(m0 - mn0), corr1 = ex2(m1 - mn1);

        uint32_t pf[4][4];
        #pragma unroll
        for (int s = 0; s < 4; s++) {
            float p00 = ex2(sacc[2 * s][0] - mn0);
            float p01 = ex2(sacc[2 * s][1] - mn0);
            float p10 = ex2(sacc[2 * s][2] - mn1);
            float p11 = ex2(sacc[2 * s][3] - mn1);
            float p20 = ex2(sacc[2 * s + 1][0] - mn0);
            float p21 = ex2(sacc[2 * s + 1][1] - mn0);
            float p30 = ex2(sacc[2 * s + 1][2] - mn1);
            float p31 = ex2(sacc[2 * s + 1][3] - mn1);
            pf[s][0] = f2h2(p00, p01);
            pf[s][1] = f2h2(p10, p11);
            pf[s][2] = f2h2(p20, p21);
            pf[s][3] = f2h2(p30, p31);
        }

        float lacc[4] = {0.f, 0.f, 0.f, 0.f};
        #pragma unroll
        for (int s = 0; s < 4; s++)
            MMA_F16R(lacc, pf[s][0], pf[s][1], pf[s][2], pf[s][3], ONES, ONES);

        l0 = l0 * corr0 + lacc[0];
        l1 = l1 * corr1 + lacc[2];
        m0 = mn0; m1 = mn1;
        #pragma unroll
        for (int nt = 0; nt < 8; nt++) {
            o[nt][0] *= corr0; o[nt][1] *= corr0;
            o[nt][2] *= corr1; o[nt][3] *= corr1;
        }

        #pragma unroll
        for (int s = 0; s < 4; s++) {
            #pragma unroll
            for (int np = 0; np < 4; np++) {
                uint32_t v0, v1, v2, v3;
                LDSM4T(v0, v1, v2, v3, vBase + (uint32_t)(s * 16 * PKH + np * 8) * 4);
                MMA_F16R(o[2 * np],     pf[s][0], pf[s][1], pf[s][2], pf[s][3], v0, v1);
                MMA_F16R(o[2 * np + 1], pf[s][0], pf[s][1], pf[s][2], pf[s][3], v2, v3);
            }
        }
    }

    uint32_t* Ab = g_Ah + (size_t)b * QLEN * KP + h * 32;
    float i0 = 1.f / l0, i1 = 1.f / l1;
    int r0 = q0 + mrow + g;
    #pragma unroll
    for (int nt = 0; nt < 8; nt++) {
        int colp = nt * 4 + tg;
        Ab[(size_t)r0 * KP + colp]       = f2h2(o[nt][0] * i0, o[nt][1] * i0);
        Ab[(size_t)(r0 + 8) * KP + colp] = f2h2(o[nt][2] * i1, o[nt][3] * i1);
    }
}

// ---------------------------------------------------------------------------
extern "C" void kernel_launch(void* const* d_in, const int* in_sizes, int n_in,
                              void* d_out, int out_size)
{
    const float* query   = (const float*)d_in[0];
    const float* context = (const float*)d_in[1];
    const float* Wq = (const float*)d_in[2];
    const float* bq = (const float*)d_in[3];
    const float* Wk = (const float*)d_in[4];
    const float* bk = (const float*)d_in[5];
    const float* Wv = (const float*)d_in[6];
    const float* bv = (const float*)d_in[7];
    const float* Wo = (const float*)d_in[8];
    const float* bo = (const float*)d_in[9];
    float* out = (float*)d_out;

    prepack_kernel<<<dim3(EMBED / 64, EMBED / 32, 6), 256>>>(query, context, Wq, Wk, Wv, Wo);

    cudaFuncSetAttribute(gemm_qkv_kernel,
                         cudaFuncAttributeMaxDynamicSharedMemorySize, GSMEM);
    cudaFuncSetAttribute(gemm_o_kernel,
                         cudaFuncAttributeMaxDynamicSharedMemorySize, GSMEM);

    dim3 gQKV(EMBED / 128, MROWS / 64, 3);   // (8, 64, 3) = 1536 CTAs
    gemm_qkv_kernel<<<gQKV, 128, GSMEM>>>(bq, bk, bv);

    cudaFuncSetAttribute(flash_h_kernel,
                         cudaFuncAttributeMaxDynamicSharedMemorySize, FSM_TOTAL);
    flash_h_kernel<<<dim3(QLEN / 128, NHEADS, BATCH), 256, FSM_TOTAL>>>();

    dim3 gGemm(EMBED / 128, MROWS / 64);     // (8, 64) = 512 CTAs
    gemm_o_kernel<<<gGemm, 128, GSMEM>>>(bo, out);
}

// round 15
// speedup vs baseline: 1.1767x; 1.1767x over previous
#include <cuda_runtime.h>
#include <math.h>
#include <stdint.h>

#define EMBED   1024
#define NHEADS  16
#define HDIM    64
#define BATCH   2
#define QLEN    2048
#define CLEN    2048
#define MROWS   (BATCH * QLEN)   // 4096
#define KP      (EMBED / 2)      // 512 u32 pairs per row

__device__ __align__(16) uint32_t g_Xqh[MROWS * KP];
__device__ __align__(16) uint32_t g_Xch[MROWS * KP];
__device__ __align__(16) uint32_t g_Wt[4][EMBED * KP];   // transposed: [n][kp]
__device__ __align__(16) uint32_t g_Qh[MROWS * KP];      // Q * (0.125*log2e) fp16
__device__ __align__(16) uint32_t g_Kh[MROWS * KP];
__device__ __align__(16) uint32_t g_Vh[MROWS * KP];
__device__ __align__(16) uint32_t g_Ah[MROWS * KP];

__device__ __forceinline__ uint32_t f2h2(float lo, float hi) {
    uint32_t r;
    asm("cvt.rn.f16x2.f32 %0, %1, %2;" : "=r"(r) : "f"(hi), "f"(lo));
    return r;
}
__device__ __forceinline__ float ex2(float x) {
    float y;
    asm("ex2.approx.ftz.f32 %0, %1;" : "=f"(y) : "f"(x));
    return y;
}
__device__ __forceinline__ uint32_t smem_u32(const void* p) {
    return (uint32_t)__cvta_generic_to_shared(p);
}
__device__ __forceinline__ void cp16(uint32_t saddr, const void* g) {
    asm volatile("cp.async.cg.shared.global [%0], [%1], 16;" :: "r"(saddr), "l"(g));
}
#define CP_COMMIT() asm volatile("cp.async.commit_group;" ::: "memory")
#define CP_WAIT(n)  asm volatile("cp.async.wait_group %0;" :: "n"(n) : "memory")

#define LDSM4(r0, r1, r2, r3, a)                                           \
    asm volatile("ldmatrix.sync.aligned.m8n8.x4.shared.b16 {%0,%1,%2,%3}, [%4];" \
        : "=r"(r0), "=r"(r1), "=r"(r2), "=r"(r3) : "r"(a))
#define LDSM4T(r0, r1, r2, r3, a)                                          \
    asm volatile("ldmatrix.sync.aligned.m8n8.x4.trans.shared.b16 {%0,%1,%2,%3}, [%4];" \
        : "=r"(r0), "=r"(r1), "=r"(r2), "=r"(r3) : "r"(a))

#define MMA_F16R(d, a0, a1, a2, a3, b0, b1)                                \
    asm volatile(                                                          \
        "mma.sync.aligned.m16n8k16.row.col.f32.f16.f16.f32 "               \
        "{%0,%1,%2,%3}, {%4,%5,%6,%7}, {%8,%9}, {%0,%1,%2,%3};"            \
        : "+f"(d[0]), "+f"(d[1]), "+f"(d[2]), "+f"(d[3])                   \
        : "r"(a0), "r"(a1), "r"(a2), "r"(a3), "r"(b0), "r"(b1))

// ---------------------------------------------------------------------------
// Prepass (single launch): z=0,1 pack inputs; z=2..5 transpose+pack weights.
// ---------------------------------------------------------------------------
__global__ void __launch_bounds__(256) prepack_kernel(
    const float* __restrict__ q, const float* __restrict__ ctx,
    const float* __restrict__ Wq, const float* __restrict__ Wk,
    const float* __restrict__ Wv, const float* __restrict__ Wo)
{
    const int z = blockIdx.z;
    const int tid = threadIdx.x;

    if (z < 2) {
        const float* src = (z == 0) ? q : ctx;
        uint2* dst = (uint2*)((z == 0) ? g_Xqh : g_Xch);
        const int blk = blockIdx.y * gridDim.x + blockIdx.x;
        const int stride = gridDim.x * gridDim.y * 256;
        const int count = MROWS * KP / 2;
        for (int i = blk * 256 + tid; i < count; i += stride) {
            float4 v = ((const float4*)src)[i];
            dst[i] = make_uint2(f2h2(v.x, v.y), f2h2(v.z, v.w));
        }
    } else {
        __shared__ float ws[64][33];
        const float* W = (z == 2) ? Wq : (z == 3) ? Wk : (z == 4) ? Wv : Wo;
        uint32_t* Wt = g_Wt[z - 2];
        const int kb = blockIdx.x * 64;
        const int nb = blockIdx.y * 32;
        #pragma unroll
        for (int i = 0; i < 8; i++) {
            int idx = tid + i * 256;
            int r = idx >> 5;
            int c = idx & 31;
            ws[r][c] = W[(size_t)(kb + r) * EMBED + nb + c];
        }
        __syncthreads();
        #pragma unroll
        for (int i = 0; i < 4; i++) {
            int idx = tid + i * 256;
            int n  = idx >> 5;
            int kp = idx & 31;
            Wt[(size_t)(nb + n) * KP + (kb >> 1) + kp] =
                f2h2(ws[2 * kp][n], ws[2 * kp + 1][n]);
        }
    }
}

// ---------------------------------------------------------------------------
// fp16 GEMM + bias: 4-stage cp.async ring, BK=32, issue hoisted above MMA.
// CTA 128x128, 256 threads (8 warps 2x4), warp tile 64x32 (R12 shape).
// ---------------------------------------------------------------------------
#define NSTG 4
#define PT   20
#define TSTG (128 * PT)
#define GSMEM ((NSTG * 2 * TSTG) * 4)   // 81920 B

__device__ __forceinline__ void gemm_h_body(
    const uint32_t* __restrict__ A, const uint32_t* __restrict__ Wt,
    const float* __restrict__ bias, void* __restrict__ Cout,
    int outHalf, float oscale, int bx, int by)
{
    extern __shared__ uint32_t gsm[];
    uint32_t* As = gsm;
    uint32_t* Bs = gsm + NSTG * TSTG;
    const uint32_t sAs = smem_u32(As);
    const uint32_t sBs = smem_u32(Bs);

    const int tid  = threadIdx.x;
    const int lane = tid & 31;
    const int warp = tid >> 5;
    const int g    = lane >> 2;
    const int tg   = lane & 3;
    const int wr   = (warp >> 2) * 64;
    const int wc   = (warp & 3) * 32;
    const int rowBase = by * 128;
    const int colBase = bx * 128;
    const int KT = 32;

    const int arow  = wr + ((lane >> 3) & 1) * 8 + (lane & 7);
    const int ahalf = ((lane >> 4) & 1) * 4;
    const int brow  = wc + ((lane >> 4) & 1) * 8 + (lane & 7);
    const int bhalf = ((lane >> 3) & 1) * 4;

    const int c0 = 2 * tid, c1 = 2 * tid + 1;
    const int r0_ = c0 >> 2, q0_ = (c0 & 3) * 4;
    const int r1_ = c1 >> 2, q1_ = (c1 & 3) * 4;

    const uint32_t* A0 = A  + (size_t)(rowBase + r0_) * KP + q0_;
    const uint32_t* A1 = A  + (size_t)(rowBase + r1_) * KP + q1_;
    const uint32_t* B0 = Wt + (size_t)(colBase + r0_) * KP + q0_;
    const uint32_t* B1 = Wt + (size_t)(colBase + r1_) * KP + q1_;

    auto issue = [&](int stg, int kt) {
        uint32_t sa = sAs + (uint32_t)(stg * TSTG) * 4;
        uint32_t sb = sBs + (uint32_t)(stg * TSTG) * 4;
        cp16(sa + (r0_ * PT + q0_) * 4, A0 + kt * 16);
        cp16(sa + (r1_ * PT + q1_) * 4, A1 + kt * 16);
        cp16(sb + (r0_ * PT + q0_) * 4, B0 + kt * 16);
        cp16(sb + (r1_ * PT + q1_) * 4, B1 + kt * 16);
        CP_COMMIT();
    };

    float acc[4][4][4];
    #pragma unroll
    for (int mt = 0; mt < 4; mt++)
        #pragma unroll
        for (int nt = 0; nt < 4; nt++)
            #pragma unroll
            for (int e = 0; e < 4; e++) acc[mt][nt][e] = 0.f;

    issue(0, 0);
    issue(1, 1);
    issue(2, 2);

    for (int kt = 0; kt < KT; kt++) {
        const int stg = kt & 3;
        // wait until group kt is complete (count = groups still legitimately pending)
        if (kt + 3 <= KT)      { CP_WAIT(2); }
        else if (kt + 2 <= KT) { CP_WAIT(1); }
        else                   { CP_WAIT(0); }
        __syncthreads();
        // stage (kt+3)&3 was consumed at kt-1; barrier above covers all warps.
        if (kt + 3 < KT) issue((kt + 3) & 3, kt + 3);

        const uint32_t aBase = sAs + (uint32_t)(stg * TSTG) * 4;
        const uint32_t bBase = sBs + (uint32_t)(stg * TSTG) * 4;

        #pragma unroll
        for (int s = 0; s < 2; s++) {
            uint32_t a[4][4];
            #pragma unroll
            for (int mt = 0; mt < 4; mt++)
                LDSM4(a[mt][0], a[mt][1], a[mt][2], a[mt][3],
                      aBase + (uint32_t)(((arow + mt * 16) * PT) + 8 * s + ahalf) * 4);
            #pragma unroll
            for (int ntp = 0; ntp < 2; ntp++) {
                uint32_t b0, b1, b2, b3;
                LDSM4(b0, b1, b2, b3,
                      bBase + (uint32_t)(((brow + ntp * 16) * PT) + 8 * s + bhalf) * 4);
                #pragma unroll
                for (int mt = 0; mt < 4; mt++) {
                    MMA_F16R(acc[mt][2 * ntp],     a[mt][0], a[mt][1], a[mt][2], a[mt][3], b0, b1);
                    MMA_F16R(acc[mt][2 * ntp + 1], a[mt][0], a[mt][1], a[mt][2], a[mt][3], b2, b3);
                }
            }
        }
    }

    if (outHalf) {
        uint32_t* C = (uint32_t*)Cout;
        #pragma unroll
        for (int mt = 0; mt < 4; mt++) {
            #pragma unroll
            for (int nt = 0; nt < 4; nt++) {
                int row  = rowBase + wr + mt * 16 + g;
                int col  = colBase + wc + nt * 8 + 2 * tg;
                int colp = col >> 1;
                float2 bv = *(const float2*)&bias[col];
                C[(size_t)row * KP + colp] =
                    f2h2((acc[mt][nt][0] + bv.x) * oscale,
                         (acc[mt][nt][1] + bv.y) * oscale);
                C[(size_t)(row + 8) * KP + colp] =
                    f2h2((acc[mt][nt][2] + bv.x) * oscale,
                         (acc[mt][nt][3] + bv.y) * oscale);
            }
        }
    } else {
        float* C = (float*)Cout;
        #pragma unroll
        for (int mt = 0; mt < 4; mt++) {
            #pragma unroll
            for (int nt = 0; nt < 4; nt++) {
                int row = rowBase + wr + mt * 16 + g;
                int col = colBase + wc + nt * 8 + 2 * tg;
                float2 bv = *(const float2*)&bias[col];
                float2 r0 = make_float2(acc[mt][nt][0] + bv.x, acc[mt][nt][1] + bv.y);
                float2 r1 = make_float2(acc[mt][nt][2] + bv.x, acc[mt][nt][3] + bv.y);
                *(float2*)&C[(size_t)row * EMBED + col]       = r0;
                *(float2*)&C[(size_t)(row + 8) * EMBED + col] = r1;
            }
        }
    }
}

#define QSCALE (0.125f * 1.44269504f)

__global__ void __launch_bounds__(256, 2) gemm_qkv_kernel(
    const float* __restrict__ bq, const float* __restrict__ bk,
    const float* __restrict__ bv)
{
    const int z = blockIdx.z;
    if (z == 0)      gemm_h_body(g_Xqh, g_Wt[0], bq, g_Qh, 1, QSCALE, blockIdx.x, blockIdx.y);
    else if (z == 1) gemm_h_body(g_Xch, g_Wt[1], bk, g_Kh, 1, 1.0f,   blockIdx.x, blockIdx.y);
    else             gemm_h_body(g_Xch, g_Wt[2], bv, g_Vh, 1, 1.0f,   blockIdx.x, blockIdx.y);
}

__global__ void __launch_bounds__(256, 2) gemm_o_kernel(
    const float* __restrict__ bo, float* __restrict__ out)
{
    gemm_h_body(g_Ah, g_Wt[3], bo, out, 0, 1.0f, blockIdx.x, blockIdx.y);
}

// ---------------------------------------------------------------------------
// Flash attention fp16 (R12 best, byte-identical): 8 warps x 16 q-rows,
// 3-stage cp.async KV ring, one barrier per tile, ones-MMA row sums,
// P in registers, exp2-domain softmax.
// ---------------------------------------------------------------------------
#define FST  3
#define PKH 36
#define PPH 36
#define FSM_TOTAL ((FST * 2 * 64 * PKH + 128 * PPH) * 4)   // 73728 B

__global__ void __launch_bounds__(256, 2) flash_h_kernel()
{
    extern __shared__ uint32_t sm[];
    uint32_t* Ks = sm;
    uint32_t* Vs = sm + FST * 64 * PKH;
    uint32_t* Qstage = sm + 2 * FST * 64 * PKH;

    const int b  = blockIdx.z;
    const int h  = blockIdx.y;
    const int q0 = blockIdx.x * 128;
    const int tid  = threadIdx.x;
    const int lane = tid & 31;
    const int warp = tid >> 5;
    const int g    = lane >> 2;
    const int tg   = lane & 3;
    const int mrow = warp * 16;

    const int krow  = ((lane >> 4) & 1) * 8 + (lane & 7);
    const int khalf = ((lane >> 3) & 1) * 4;
    const int vk = ((lane >> 3) & 1) * 8 + (lane & 7);
    const int vd = ((lane >> 4) & 1) * 4;

    const uint32_t* Qb = g_Qh + (size_t)b * QLEN * KP + h * 32;
    const uint32_t* Kb = g_Kh + (size_t)b * CLEN * KP + h * 32;
    const uint32_t* Vb = g_Vh + (size_t)b * CLEN * KP + h * 32;

    const int c0 = 2 * tid, c1 = 2 * tid + 1;
    const int cr0 = c0 >> 3, cc0 = (c0 & 7) * 4;
    const int cr1 = c1 >> 3, cc1 = (c1 & 7) * 4;
    const uint32_t sKs = smem_u32(Ks);
    const uint32_t sVs = smem_u32(Vs);

    auto issueKV = [&](int stg, int kt) {
        uint32_t ks = sKs + (uint32_t)(stg * 64 * PKH) * 4;
        uint32_t vs = sVs + (uint32_t)(stg * 64 * PKH) * 4;
        cp16(ks + (uint32_t)(cr0 * PKH + cc0) * 4, Kb + (size_t)(kt * 64 + cr0) * KP + cc0);
        cp16(ks + (uint32_t)(cr1 * PKH + cc1) * 4, Kb + (size_t)(kt * 64 + cr1) * KP + cc1);
        cp16(vs + (uint32_t)(cr0 * PKH + cc0) * 4, Vb + (size_t)(kt * 64 + cr0) * KP + cc0);
        cp16(vs + (uint32_t)(cr1 * PKH + cc1) * 4, Vb + (size_t)(kt * 64 + cr1) * KP + cc1);
        CP_COMMIT();
    };

    #pragma unroll
    for (int i = 0; i < 4; i++) {
        int idx = tid + i * 256;
        int r = idx >> 3;
        int c = (idx & 7) * 4;
        uint4 v = *(const uint4*)&Qb[(size_t)(q0 + r) * KP + c];
        *(uint4*)&Qstage[r * PPH + c] = v;
    }
    issueKV(0, 0);
    issueKV(1, 1);
    __syncthreads();

    uint32_t qf[4][4];
    #pragma unroll
    for (int s = 0; s < 4; s++) {
        qf[s][0] = Qstage[(mrow + g) * PPH + 8 * s + tg];
        qf[s][1] = Qstage[(mrow + g + 8) * PPH + 8 * s + tg];
        qf[s][2] = Qstage[(mrow + g) * PPH + 8 * s + tg + 4];
        qf[s][3] = Qstage[(mrow + g + 8) * PPH + 8 * s + tg + 4];
    }

    const uint32_t ONES = 0x3C003C00u;
    float m0 = -INFINITY, m1 = -INFINITY, l0 = 0.f, l1 = 0.f;
    float o[8][4];
    #pragma unroll
    for (int nt = 0; nt < 8; nt++)
        #pragma unroll
        for (int e = 0; e < 4; e++) o[nt][e] = 0.f;

    const int NT = CLEN / 64;
    for (int kt = 0; kt < NT; kt++) {
        const int stg = kt % FST;
        if (kt + 1 < NT) { CP_WAIT(1); } else { CP_WAIT(0); }
        __syncthreads();
        if (kt + 2 < NT) issueKV((kt + 2) % FST, kt + 2);

        const uint32_t kBase = sKs + (uint32_t)(stg * 64 * PKH + krow * PKH + khalf) * 4;
        const uint32_t vBase = sVs + (uint32_t)(stg * 64 * PKH + vk * PKH + vd) * 4;

        float sacc[8][4];
        #pragma unroll
        for (int nt = 0; nt < 8; nt++)
            #pragma unroll
            for (int e = 0; e < 4; e++) sacc[nt][e] = 0.f;

        #pragma unroll
        for (int s = 0; s < 4; s++) {
            #pragma unroll
            for (int ntp = 0; ntp < 4; ntp++) {
                uint32_t b0, b1, b2, b3;
                LDSM4(b0, b1, b2, b3, kBase + (uint32_t)(ntp * 16 * PKH + 8 * s) * 4);
                MMA_F16R(sacc[2 * ntp],     qf[s][0], qf[s][1], qf[s][2], qf[s][3], b0, b1);
                MMA_F16R(sacc[2 * ntp + 1], qf[s][0], qf[s][1], qf[s][2], qf[s][3], b2, b3);
            }
        }

        float mx0 = -INFINITY, mx1 = -INFINITY;
        #pragma unroll
        for (int nt = 0; nt < 8; nt++) {
            mx0 = fmaxf(mx0, fmaxf(sacc[nt][0], sacc[nt][1]));
            mx1 = fmaxf(mx1, fmaxf(sacc[nt][2], sacc[nt][3]));
        }
        #pragma unroll
        for (int off = 1; off < 4; off <<= 1) {
            mx0 = fmaxf(mx0, __shfl_xor_sync(0xffffffffu, mx0, off));
            mx1 = fmaxf(mx1, __shfl_xor_sync(0xffffffffu, mx1, off));
        }
        float mn0 = fmaxf(m0, mx0), mn1 = fmaxf(m1, mx1);
        float corr0 = ex2(m0 - mn0), corr1 = ex2(m1 - mn1);

        uint32_t pf[4][4];
        #pragma unroll
        for (int s = 0; s < 4; s++) {
            float p00 = ex2(sacc[2 * s][0] - mn0);
            float p01 = ex2(sacc[2 * s][1] - mn0);
            float p10 = ex2(sacc[2 * s][2] - mn1);
            float p11 = ex2(sacc[2 * s][3] - mn1);
            float p20 = ex2(sacc[2 * s + 1][0] - mn0);
            float p21 = ex2(sacc[2 * s + 1][1] - mn0);
            float p30 = ex2(sacc[2 * s + 1][2] - mn1);
            float p31 = ex2(sacc[2 * s + 1][3] - mn1);
            pf[s][0] = f2h2(p00, p01);
            pf[s][1] = f2h2(p10, p11);
            pf[s][2] = f2h2(p20, p21);
            pf[s][3] = f2h2(p30, p31);
        }

        float lacc[4] = {0.f, 0.f, 0.f, 0.f};
        #pragma unroll
        for (int s = 0; s < 4; s++)
            MMA_F16R(lacc, pf[s][0], pf[s][1], pf[s][2], pf[s][3], ONES, ONES);

        l0 = l0 * corr0 + lacc[0];
        l1 = l1 * corr1 + lacc[2];
        m0 = mn0; m1 = mn1;
        #pragma unroll
        for (int nt = 0; nt < 8; nt++) {
            o[nt][0] *= corr0; o[nt][1] *= corr0;
            o[nt][2] *= corr1; o[nt][3] *= corr1;
        }

        #pragma unroll
        for (int s = 0; s < 4; s++) {
            #pragma unroll
            for (int np = 0; np < 4; np++) {
                uint32_t v0, v1, v2, v3;
                LDSM4T(v0, v1, v2, v3, vBase + (uint32_t)(s * 16 * PKH + np * 8) * 4);
                MMA_F16R(o[2 * np],     pf[s][0], pf[s][1], pf[s][2], pf[s][3], v0, v1);
                MMA_F16R(o[2 * np + 1], pf[s][0], pf[s][1], pf[s][2], pf[s][3], v2, v3);
            }
        }
    }

    uint32_t* Ab = g_Ah + (size_t)b * QLEN * KP + h * 32;
    float i0 = 1.f / l0, i1 = 1.f / l1;
    int r0 = q0 + mrow + g;
    #pragma unroll
    for (int nt = 0; nt < 8; nt++) {
        int colp = nt * 4 + tg;
        Ab[(size_t)r0 * KP + colp]       = f2h2(o[nt][0] * i0, o[nt][1] * i0);
        Ab[(size_t)(r0 + 8) * KP + colp] = f2h2(o[nt][2] * i1, o[nt][3] * i1);
    }
}

// ---------------------------------------------------------------------------
extern "C" void kernel_launch(void* const* d_in, const int* in_sizes, int n_in,
                              void* d_out, int out_size)
{
    const float* query   = (const float*)d_in[0];
    const float* context = (const float*)d_in[1];
    const float* Wq = (const float*)d_in[2];
    const float* bq = (const float*)d_in[3];
    const float* Wk = (const float*)d_in[4];
    const float* bk = (const float*)d_in[5];
    const float* Wv = (const float*)d_in[6];
    const float* bv = (const float*)d_in[7];
    const float* Wo = (const float*)d_in[8];
    const float* bo = (const float*)d_in[9];
    float* out = (float*)d_out;

    prepack_kernel<<<dim3(EMBED / 64, EMBED / 32, 6), 256>>>(query, context, Wq, Wk, Wv, Wo);

    cudaFuncSetAttribute(gemm_qkv_kernel,
                         cudaFuncAttributeMaxDynamicSharedMemorySize, GSMEM);
    cudaFuncSetAttribute(gemm_o_kernel,
                         cudaFuncAttributeMaxDynamicSharedMemorySize, GSMEM);

    dim3 gQKV(EMBED / 128, MROWS / 128, 3);   // (8, 32, 3)
    gemm_qkv_kernel<<<gQKV, 256, GSMEM>>>(bq, bk, bv);

    cudaFuncSetAttribute(flash_h_kernel,
                         cudaFuncAttributeMaxDynamicSharedMemorySize, FSM_TOTAL);
    flash_h_kernel<<<dim3(QLEN / 128, NHEADS, BATCH), 256, FSM_TOTAL>>>();

    dim3 gGemm(EMBED / 128, MROWS / 128);     // (8, 32)
    gemm_o_kernel<<<gGemm, 256, GSMEM>>>(bo, out);
}

// round 16
// speedup vs baseline: 1.2276x; 1.0432x over previous
#include <cuda_runtime.h>
#include <math.h>
#include <stdint.h>

#define EMBED   1024
#define NHEADS  16
#define HDIM    64
#define BATCH   2
#define QLEN    2048
#define CLEN    2048
#define MROWS   (BATCH * QLEN)   // 4096
#define KP      (EMBED / 2)      // 512 u32 pairs per row

__device__ __align__(16) uint32_t g_Xqh[MROWS * KP];
__device__ __align__(16) uint32_t g_Xch[MROWS * KP];
__device__ __align__(16) uint32_t g_Wt[4][EMBED * KP];   // transposed: [n][kp]
__device__ __align__(16) uint32_t g_Qh[MROWS * KP];      // Q * (0.125*log2e) fp16
__device__ __align__(16) uint32_t g_Kh[MROWS * KP];
__device__ __align__(16) uint32_t g_Vh[MROWS * KP];
__device__ __align__(16) uint32_t g_Ah[MROWS * KP];

__device__ __forceinline__ uint32_t f2h2(float lo, float hi) {
    uint32_t r;
    asm("cvt.rn.f16x2.f32 %0, %1, %2;" : "=r"(r) : "f"(hi), "f"(lo));
    return r;
}
__device__ __forceinline__ float ex2(float x) {
    float y;
    asm("ex2.approx.ftz.f32 %0, %1;" : "=f"(y) : "f"(x));
    return y;
}
__device__ __forceinline__ uint32_t h2ex2(uint32_t x) {
    uint32_t y;
    asm("ex2.approx.f16x2 %0, %1;" : "=r"(y) : "r"(x));
    return y;
}
__device__ __forceinline__ uint32_t smem_u32(const void* p) {
    return (uint32_t)__cvta_generic_to_shared(p);
}
__device__ __forceinline__ void cp16(uint32_t saddr, const void* g) {
    asm volatile("cp.async.cg.shared.global [%0], [%1], 16;" :: "r"(saddr), "l"(g));
}
#define CP_COMMIT() asm volatile("cp.async.commit_group;" ::: "memory")
#define CP_WAIT(n)  asm volatile("cp.async.wait_group %0;" :: "n"(n) : "memory")

#define LDSM4(r0, r1, r2, r3, a)                                           \
    asm volatile("ldmatrix.sync.aligned.m8n8.x4.shared.b16 {%0,%1,%2,%3}, [%4];" \
        : "=r"(r0), "=r"(r1), "=r"(r2), "=r"(r3) : "r"(a))
#define LDSM4T(r0, r1, r2, r3, a)                                          \
    asm volatile("ldmatrix.sync.aligned.m8n8.x4.trans.shared.b16 {%0,%1,%2,%3}, [%4];" \
        : "=r"(r0), "=r"(r1), "=r"(r2), "=r"(r3) : "r"(a))

#define MMA_F16R(d, a0, a1, a2, a3, b0, b1)                                \
    asm volatile(                                                          \
        "mma.sync.aligned.m16n8k16.row.col.f32.f16.f16.f32 "               \
        "{%0,%1,%2,%3}, {%4,%5,%6,%7}, {%8,%9}, {%0,%1,%2,%3};"            \
        : "+f"(d[0]), "+f"(d[1]), "+f"(d[2]), "+f"(d[3])                   \
        : "r"(a0), "r"(a1), "r"(a2), "r"(a3), "r"(b0), "r"(b1))

// ---------------------------------------------------------------------------
// Prepass (single launch): z=0,1 pack inputs; z=2..5 transpose+pack weights.
// ---------------------------------------------------------------------------
__global__ void __launch_bounds__(256) prepack_kernel(
    const float* __restrict__ q, const float* __restrict__ ctx,
    const float* __restrict__ Wq, const float* __restrict__ Wk,
    const float* __restrict__ Wv, const float* __restrict__ Wo)
{
    const int z = blockIdx.z;
    const int tid = threadIdx.x;

    if (z < 2) {
        const float* src = (z == 0) ? q : ctx;
        uint2* dst = (uint2*)((z == 0) ? g_Xqh : g_Xch);
        const int blk = blockIdx.y * gridDim.x + blockIdx.x;
        const int stride = gridDim.x * gridDim.y * 256;
        const int count = MROWS * KP / 2;
        for (int i = blk * 256 + tid; i < count; i += stride) {
            float4 v = ((const float4*)src)[i];
            dst[i] = make_uint2(f2h2(v.x, v.y), f2h2(v.z, v.w));
        }
    } else {
        __shared__ float ws[64][33];
        const float* W = (z == 2) ? Wq : (z == 3) ? Wk : (z == 4) ? Wv : Wo;
        uint32_t* Wt = g_Wt[z - 2];
        const int kb = blockIdx.x * 64;
        const int nb = blockIdx.y * 32;
        #pragma unroll
        for (int i = 0; i < 8; i++) {
            int idx = tid + i * 256;
            int r = idx >> 5;
            int c = idx & 31;
            ws[r][c] = W[(size_t)(kb + r) * EMBED + nb + c];
        }
        __syncthreads();
        #pragma unroll
        for (int i = 0; i < 4; i++) {
            int idx = tid + i * 256;
            int n  = idx >> 5;
            int kp = idx & 31;
            Wt[(size_t)(nb + n) * KP + (kb >> 1) + kp] =
                f2h2(ws[2 * kp][n], ws[2 * kp + 1][n]);
        }
    }
}

// ---------------------------------------------------------------------------
// fp16 GEMM + bias: 3-stage cp.async ring, BK=32 (R12 best config, frozen).
// CTA 128x128, 256 threads (8 warps 2x4), warp tile 64x32.
// ---------------------------------------------------------------------------
#define NSTG 3
#define PT   20
#define TSTG (128 * PT)
#define GSMEM ((NSTG * 2 * TSTG) * 4)

__device__ __forceinline__ void gemm_h_body(
    const uint32_t* __restrict__ A, const uint32_t* __restrict__ Wt,
    const float* __restrict__ bias, void* __restrict__ Cout,
    int outHalf, float oscale, int bx, int by)
{
    extern __shared__ uint32_t gsm[];
    uint32_t* As = gsm;
    uint32_t* Bs = gsm + NSTG * TSTG;
    const uint32_t sAs = smem_u32(As);
    const uint32_t sBs = smem_u32(Bs);

    const int tid  = threadIdx.x;
    const int lane = tid & 31;
    const int warp = tid >> 5;
    const int g    = lane >> 2;
    const int tg   = lane & 3;
    const int wr   = (warp >> 2) * 64;
    const int wc   = (warp & 3) * 32;
    const int rowBase = by * 128;
    const int colBase = bx * 128;
    const int KT = 32;

    const int arow  = wr + ((lane >> 3) & 1) * 8 + (lane & 7);
    const int ahalf = ((lane >> 4) & 1) * 4;
    const int brow  = wc + ((lane >> 4) & 1) * 8 + (lane & 7);
    const int bhalf = ((lane >> 3) & 1) * 4;

    const int c0 = 2 * tid, c1 = 2 * tid + 1;
    const int r0_ = c0 >> 2, q0_ = (c0 & 3) * 4;
    const int r1_ = c1 >> 2, q1_ = (c1 & 3) * 4;

    const uint32_t* A0 = A  + (size_t)(rowBase + r0_) * KP + q0_;
    const uint32_t* A1 = A  + (size_t)(rowBase + r1_) * KP + q1_;
    const uint32_t* B0 = Wt + (size_t)(colBase + r0_) * KP + q0_;
    const uint32_t* B1 = Wt + (size_t)(colBase + r1_) * KP + q1_;

    auto issue = [&](int stg, int kt) {
        uint32_t sa = sAs + (uint32_t)(stg * TSTG) * 4;
        uint32_t sb = sBs + (uint32_t)(stg * TSTG) * 4;
        cp16(sa + (r0_ * PT + q0_) * 4, A0 + kt * 16);
        cp16(sa + (r1_ * PT + q1_) * 4, A1 + kt * 16);
        cp16(sb + (r0_ * PT + q0_) * 4, B0 + kt * 16);
        cp16(sb + (r1_ * PT + q1_) * 4, B1 + kt * 16);
        CP_COMMIT();
    };

    float acc[4][4][4];
    #pragma unroll
    for (int mt = 0; mt < 4; mt++)
        #pragma unroll
        for (int nt = 0; nt < 4; nt++)
            #pragma unroll
            for (int e = 0; e < 4; e++) acc[mt][nt][e] = 0.f;

    issue(0, 0);
    issue(1, 1);

    for (int kt = 0; kt < KT; kt++) {
        const int stg = kt % NSTG;
        if (kt + 1 < KT) { CP_WAIT(1); } else { CP_WAIT(0); }
        __syncthreads();

        const uint32_t aBase = sAs + (uint32_t)(stg * TSTG) * 4;
        const uint32_t bBase = sBs + (uint32_t)(stg * TSTG) * 4;

        #pragma unroll
        for (int s = 0; s < 2; s++) {
            uint32_t a[4][4];
            #pragma unroll
            for (int mt = 0; mt < 4; mt++)
                LDSM4(a[mt][0], a[mt][1], a[mt][2], a[mt][3],
                      aBase + (uint32_t)(((arow + mt * 16) * PT) + 8 * s + ahalf) * 4);
            #pragma unroll
            for (int ntp = 0; ntp < 2; ntp++) {
                uint32_t b0, b1, b2, b3;
                LDSM4(b0, b1, b2, b3,
                      bBase + (uint32_t)(((brow + ntp * 16) * PT) + 8 * s + bhalf) * 4);
                #pragma unroll
                for (int mt = 0; mt < 4; mt++) {
                    MMA_F16R(acc[mt][2 * ntp],     a[mt][0], a[mt][1], a[mt][2], a[mt][3], b0, b1);
                    MMA_F16R(acc[mt][2 * ntp + 1], a[mt][0], a[mt][1], a[mt][2], a[mt][3], b2, b3);
                }
            }
        }
        if (kt + 2 < KT) issue((kt + 2) % NSTG, kt + 2);
    }

    if (outHalf) {
        uint32_t* C = (uint32_t*)Cout;
        #pragma unroll
        for (int mt = 0; mt < 4; mt++) {
            #pragma unroll
            for (int nt = 0; nt < 4; nt++) {
                int row  = rowBase + wr + mt * 16 + g;
                int col  = colBase + wc + nt * 8 + 2 * tg;
                int colp = col >> 1;
                float2 bv = *(const float2*)&bias[col];
                C[(size_t)row * KP + colp] =
                    f2h2((acc[mt][nt][0] + bv.x) * oscale,
                         (acc[mt][nt][1] + bv.y) * oscale);
                C[(size_t)(row + 8) * KP + colp] =
                    f2h2((acc[mt][nt][2] + bv.x) * oscale,
                         (acc[mt][nt][3] + bv.y) * oscale);
            }
        }
    } else {
        float* C = (float*)Cout;
        #pragma unroll
        for (int mt = 0; mt < 4; mt++) {
            #pragma unroll
            for (int nt = 0; nt < 4; nt++) {
                int row = rowBase + wr + mt * 16 + g;
                int col = colBase + wc + nt * 8 + 2 * tg;
                float2 bv = *(const float2*)&bias[col];
                float2 r0 = make_float2(acc[mt][nt][0] + bv.x, acc[mt][nt][1] + bv.y);
                float2 r1 = make_float2(acc[mt][nt][2] + bv.x, acc[mt][nt][3] + bv.y);
                *(float2*)&C[(size_t)row * EMBED + col]       = r0;
                *(float2*)&C[(size_t)(row + 8) * EMBED + col] = r1;
            }
        }
    }
}

#define QSCALE (0.125f * 1.44269504f)

__global__ void __launch_bounds__(256, 2) gemm_qkv_kernel(
    const float* __restrict__ bq, const float* __restrict__ bk,
    const float* __restrict__ bv)
{
    const int z = blockIdx.z;
    if (z == 0)      gemm_h_body(g_Xqh, g_Wt[0], bq, g_Qh, 1, QSCALE, blockIdx.x, blockIdx.y);
    else if (z == 1) gemm_h_body(g_Xch, g_Wt[1], bk, g_Kh, 1, 1.0f,   blockIdx.x, blockIdx.y);
    else             gemm_h_body(g_Xch, g_Wt[2], bv, g_Vh, 1, 1.0f,   blockIdx.x, blockIdx.y);
}

__global__ void __launch_bounds__(256, 2) gemm_o_kernel(
    const float* __restrict__ bo, float* __restrict__ out)
{
    gemm_h_body(g_Ah, g_Wt[3], bo, out, 0, 1.0f, blockIdx.x, blockIdx.y);
}

// ---------------------------------------------------------------------------
// Flash attention fp16: 8 warps x 16 q-rows, 3-stage cp.async KV ring,
// one barrier per tile, ones-MMA row sums, P in registers.
// NEW: softmax exp via ex2.approx.f16x2 (halves MUFU pressure).
// ---------------------------------------------------------------------------
#define FST  3
#define PKH 36
#define PPH 36
#define FSM_TOTAL ((FST * 2 * 64 * PKH + 128 * PPH) * 4)   // 73728 B

__global__ void __launch_bounds__(256, 2) flash_h_kernel()
{
    extern __shared__ uint32_t sm[];
    uint32_t* Ks = sm;
    uint32_t* Vs = sm + FST * 64 * PKH;
    uint32_t* Qstage = sm + 2 * FST * 64 * PKH;

    const int b  = blockIdx.z;
    const int h  = blockIdx.y;
    const int q0 = blockIdx.x * 128;
    const int tid  = threadIdx.x;
    const int lane = tid & 31;
    const int warp = tid >> 5;
    const int g    = lane >> 2;
    const int tg   = lane & 3;
    const int mrow = warp * 16;

    const int krow  = ((lane >> 4) & 1) * 8 + (lane & 7);
    const int khalf = ((lane >> 3) & 1) * 4;
    const int vk = ((lane >> 3) & 1) * 8 + (lane & 7);
    const int vd = ((lane >> 4) & 1) * 4;

    const uint32_t* Qb = g_Qh + (size_t)b * QLEN * KP + h * 32;
    const uint32_t* Kb = g_Kh + (size_t)b * CLEN * KP + h * 32;
    const uint32_t* Vb = g_Vh + (size_t)b * CLEN * KP + h * 32;

    const int c0 = 2 * tid, c1 = 2 * tid + 1;
    const int cr0 = c0 >> 3, cc0 = (c0 & 7) * 4;
    const int cr1 = c1 >> 3, cc1 = (c1 & 7) * 4;
    const uint32_t sKs = smem_u32(Ks);
    const uint32_t sVs = smem_u32(Vs);

    auto issueKV = [&](int stg, int kt) {
        uint32_t ks = sKs + (uint32_t)(stg * 64 * PKH) * 4;
        uint32_t vs = sVs + (uint32_t)(stg * 64 * PKH) * 4;
        cp16(ks + (uint32_t)(cr0 * PKH + cc0) * 4, Kb + (size_t)(kt * 64 + cr0) * KP + cc0);
        cp16(ks + (uint32_t)(cr1 * PKH + cc1) * 4, Kb + (size_t)(kt * 64 + cr1) * KP + cc1);
        cp16(vs + (uint32_t)(cr0 * PKH + cc0) * 4, Vb + (size_t)(kt * 64 + cr0) * KP + cc0);
        cp16(vs + (uint32_t)(cr1 * PKH + cc1) * 4, Vb + (size_t)(kt * 64 + cr1) * KP + cc1);
        CP_COMMIT();
    };

    #pragma unroll
    for (int i = 0; i < 4; i++) {
        int idx = tid + i * 256;
        int r = idx >> 3;
        int c = (idx & 7) * 4;
        uint4 v = *(const uint4*)&Qb[(size_t)(q0 + r) * KP + c];
        *(uint4*)&Qstage[r * PPH + c] = v;
    }
    issueKV(0, 0);
    issueKV(1, 1);
    __syncthreads();

    uint32_t qf[4][4];
    #pragma unroll
    for (int s = 0; s < 4; s++) {
        qf[s][0] = Qstage[(mrow + g) * PPH + 8 * s + tg];
        qf[s][1] = Qstage[(mrow + g + 8) * PPH + 8 * s + tg];
        qf[s][2] = Qstage[(mrow + g) * PPH + 8 * s + tg + 4];
        qf[s][3] = Qstage[(mrow + g + 8) * PPH + 8 * s + tg + 4];
    }

    const uint32_t ONES = 0x3C003C00u;
    float m0 = -INFINITY, m1 = -INFINITY, l0 = 0.f, l1 = 0.f;
    float o[8][4];
    #pragma unroll
    for (int nt = 0; nt < 8; nt++)
        #pragma unroll
        for (int e = 0; e < 4; e++) o[nt][e] = 0.f;

    const int NT = CLEN / 64;
    for (int kt = 0; kt < NT; kt++) {
        const int stg = kt % FST;
        if (kt + 1 < NT) { CP_WAIT(1); } else { CP_WAIT(0); }
        __syncthreads();
        if (kt + 2 < NT) issueKV((kt + 2) % FST, kt + 2);

        const uint32_t kBase = sKs + (uint32_t)(stg * 64 * PKH + krow * PKH + khalf) * 4;
        const uint32_t vBase = sVs + (uint32_t)(stg * 64 * PKH + vk * PKH + vd) * 4;

        float sacc[8][4];
        #pragma unroll
        for (int nt = 0; nt < 8; nt++)
            #pragma unroll
            for (int e = 0; e < 4; e++) sacc[nt][e] = 0.f;

        #pragma unroll
        for (int s = 0; s < 4; s++) {
            #pragma unroll
            for (int ntp = 0; ntp < 4; ntp++) {
                uint32_t b0, b1, b2, b3;
                LDSM4(b0, b1, b2, b3, kBase + (uint32_t)(ntp * 16 * PKH + 8 * s) * 4);
                MMA_F16R(sacc[2 * ntp],     qf[s][0], qf[s][1], qf[s][2], qf[s][3], b0, b1);
                MMA_F16R(sacc[2 * ntp + 1], qf[s][0], qf[s][1], qf[s][2], qf[s][3], b2, b3);
            }
        }

        float mx0 = -INFINITY, mx1 = -INFINITY;
        #pragma unroll
        for (int nt = 0; nt < 8; nt++) {
            mx0 = fmaxf(mx0, fmaxf(sacc[nt][0], sacc[nt][1]));
            mx1 = fmaxf(mx1, fmaxf(sacc[nt][2], sacc[nt][3]));
        }
        #pragma unroll
        for (int off = 1; off < 4; off <<= 1) {
            mx0 = fmaxf(mx0, __shfl_xor_sync(0xffffffffu, mx0, off));
            mx1 = fmaxf(mx1, __shfl_xor_sync(0xffffffffu, mx1, off));
        }
        float mn0 = fmaxf(m0, mx0), mn1 = fmaxf(m1, mx1);
        float corr0 = ex2(m0 - mn0), corr1 = ex2(m1 - mn1);

        // pack (s - m) into fp16 pairs, exponentiate on MUFU in f16x2 (half the ops)
        uint32_t pf[4][4];
        #pragma unroll
        for (int s = 0; s < 4; s++) {
            pf[s][0] = h2ex2(f2h2(sacc[2 * s][0] - mn0,     sacc[2 * s][1] - mn0));
            pf[s][1] = h2ex2(f2h2(sacc[2 * s][2] - mn1,     sacc[2 * s][3] - mn1));
            pf[s][2] = h2ex2(f2h2(sacc[2 * s + 1][0] - mn0, sacc[2 * s + 1][1] - mn0));
            pf[s][3] = h2ex2(f2h2(sacc[2 * s + 1][2] - mn1, sacc[2 * s + 1][3] - mn1));
        }

        float lacc[4] = {0.f, 0.f, 0.f, 0.f};
        #pragma unroll
        for (int s = 0; s < 4; s++)
            MMA_F16R(lacc, pf[s][0], pf[s][1], pf[s][2], pf[s][3], ONES, ONES);

        l0 = l0 * corr0 + lacc[0];
        l1 = l1 * corr1 + lacc[2];
        m0 = mn0; m1 = mn1;
        #pragma unroll
        for (int nt = 0; nt < 8; nt++) {
            o[nt][0] *= corr0; o[nt][1] *= corr0;
            o[nt][2] *= corr1; o[nt][3] *= corr1;
        }

        #pragma unroll
        for (int s = 0; s < 4; s++) {
            #pragma unroll
            for (int np = 0; np < 4; np++) {
                uint32_t v0, v1, v2, v3;
                LDSM4T(v0, v1, v2, v3, vBase + (uint32_t)(s * 16 * PKH + np * 8) * 4);
                MMA_F16R(o[2 * np],     pf[s][0], pf[s][1], pf[s][2], pf[s][3], v0, v1);
                MMA_F16R(o[2 * np + 1], pf[s][0], pf[s][1], pf[s][2], pf[s][3], v2, v3);
            }
        }
    }

    uint32_t* Ab = g_Ah + (size_t)b * QLEN * KP + h * 32;
    float i0 = 1.f / l0, i1 = 1.f / l1;
    int r0 = q0 + mrow + g;
    #pragma unroll
    for (int nt = 0; nt < 8; nt++) {
        int colp = nt * 4 + tg;
        Ab[(size_t)r0 * KP + colp]       = f2h2(o[nt][0] * i0, o[nt][1] * i0);
        Ab[(size_t)(r0 + 8) * KP + colp] = f2h2(o[nt][2] * i1, o[nt][3] * i1);
    }
}

// ---------------------------------------------------------------------------
extern "C" void kernel_launch(void* const* d_in, const int* in_sizes, int n_in,
                              void* d_out, int out_size)
{
    const float* query   = (const float*)d_in[0];
    const float* context = (const float*)d_in[1];
    const float* Wq = (const float*)d_in[2];
    const float* bq = (const float*)d_in[3];
    const float* Wk = (const float*)d_in[4];
    const float* bk = (const float*)d_in[5];
    const float* Wv = (const float*)d_in[6];
    const float* bv = (const float*)d_in[7];
    const float* Wo = (const float*)d_in[8];
    const float* bo = (const float*)d_in[9];
    float* out = (float*)d_out;

    prepack_kernel<<<dim3(EMBED / 64, EMBED / 32, 6), 256>>>(query, context, Wq, Wk, Wv, Wo);

    cudaFuncSetAttribute(gemm_qkv_kernel,
                         cudaFuncAttributeMaxDynamicSharedMemorySize, GSMEM);
    cudaFuncSetAttribute(gemm_o_kernel,
                         cudaFuncAttributeMaxDynamicSharedMemorySize, GSMEM);

    dim3 gQKV(EMBED / 128, MROWS / 128, 3);   // (8, 32, 3)
    gemm_qkv_kernel<<<gQKV, 256, GSMEM>>>(bq, bk, bv);

    cudaFuncSetAttribute(flash_h_kernel,
                         cudaFuncAttributeMaxDynamicSharedMemorySize, FSM_TOTAL);
    flash_h_kernel<<<dim3(QLEN / 128, NHEADS, BATCH), 256, FSM_TOTAL>>>();

    dim3 gGemm(EMBED / 128, MROWS / 128);     // (8, 32)
    gemm_o_kernel<<<gGemm, 256, GSMEM>>>(bo, out);
}